// round 10
// baseline (speedup 1.0000x reference)
#include <cuda_runtime.h>

// SelMul: pair (i,j), i<=j, row-major triangular:
//   offset(i,j) = i*N - T(i+1) + j,  T(k) = k(k-1)/2,  value x[b,i]*x[b,j].
// x: (256,1024) fp32 -> out: (256,524800) fp32 (~537 MB). Store-bound.
//
// R9 = R8 (proven-correct octet tiling) with occupancy/MLP geometry changes:
//  - 128-thread CTAs, __launch_bounds__(128,12) -> 12 CTAs/SM (1536 thr/SM).
//  - Each thread handles two windows t, t+128 per octet (unrolled) -> 8
//    independent LDG.128 in flight before dependent stores (covers L2 latency).
// Indexing identical to R8:
//  Octet rows i0..i0+7, i0%8==0; first aligned j for row r is i0 + D(r),
//  D(r) = r + ((T(r+1)&3 - r) & 3) = {0,1,3,6,6,7,9,8}, max D+3 = 12.
//  Window t: w[0..15] = x[i0+4t..i0+4t+15] (4 aligned LDG.128, clamped
//  overfetch only feeds predicated-off lanes); row r emits one aligned STG.128.
//  Heads/tails (<=3+3 elems) by scalar threads 0..15, same congruence.

static constexpr int N       = 1024;
static constexpr int B       = 256;
static constexpr int TRI     = N * (N + 1) / 2;   // 524800
static constexpr int BB      = 4;                 // batches per block
static constexpr int THREADS = 128;
static constexpr int M4LAST  = N / 4 - 1;         // 255

__host__ __device__ constexpr int triang(int k) { return k * (k - 1) / 2; }
__host__ __device__ constexpr int Dof(int r) {
    return r + ((((triang(r + 1) & 3) - r) + 8) & 3);
}

template <int K>
__device__ __forceinline__ float pick(const float4& a, const float4& b,
                                      const float4& c, const float4& d) {
    if constexpr (K == 0)  return a.x;
    else if constexpr (K == 1)  return a.y;
    else if constexpr (K == 2)  return a.z;
    else if constexpr (K == 3)  return a.w;
    else if constexpr (K == 4)  return b.x;
    else if constexpr (K == 5)  return b.y;
    else if constexpr (K == 6)  return b.z;
    else if constexpr (K == 7)  return b.w;
    else if constexpr (K == 8)  return c.x;
    else if constexpr (K == 9)  return c.y;
    else if constexpr (K == 10) return c.z;
    else if constexpr (K == 11) return c.w;
    else if constexpr (K == 12) return d.x;
    else if constexpr (K == 13) return d.y;
    else if constexpr (K == 14) return d.z;
    else return d.w;
}

template <int R>
__device__ __forceinline__ void octet_row(const float4& w0, const float4& w1,
                                          const float4& w2, const float4& w3,
                                          const float4& xq0, const float4& xq1,
                                          float* __restrict__ outb,
                                          int i0, int t) {
    constexpr int D = Dof(R);
    const int v = N - i0 - D;            // 4*n_r (may be <= 0 for last octet)
    if (v <= 0) return;
    if (t < (v >> 2)) {
        const int i = i0 + R;
        const float xi = pick<R>(xq0, xq1, xq1, xq1);       // x[i0+R]
        const int base = i * N - triang(i + 1);
        float4 o;
        o.x = pick<D    >(w0, w1, w2, w3) * xi;
        o.y = pick<D + 1>(w0, w1, w2, w3) * xi;
        o.z = pick<D + 2>(w0, w1, w2, w3) * xi;
        o.w = pick<D + 3>(w0, w1, w2, w3) * xi;
        // (base + i0 + D) % 4 == 0 by construction -> aligned STG.128
        __stcs(reinterpret_cast<float4*>(outb + base + i0 + D) + t, o);
    }
}

__device__ __forceinline__ void octet(const float4* __restrict__ xr4,
                                      float* __restrict__ outb,
                                      int i0, int t0) {
    const int nmax = (N - i0) >> 2;      // row r=0 has D=0 -> largest n
    const float4 xq0 = __ldg(xr4 + (i0 >> 2));       // x[i0..i0+3]
    const float4 xq1 = __ldg(xr4 + (i0 >> 2) + 1);   // x[i0+4..i0+7]
    // Two windows per thread (nmax <= 256 = 2*THREADS); unrolled so all 8
    // LDG.128 issue before the dependent stores.
    #pragma unroll
    for (int u = 0; u < 2; ++u) {
        const int t = t0 + u * THREADS;
        if (t >= nmax) break;
        const int m = (i0 >> 2) + t;
        // Clamped overfetch: needed x index 4m+k (k<=15) <= N-1 implies the
        // containing word m + k/4 <= M4LAST; clamps never feed active lanes.
        const float4 w0 = __ldg(xr4 + m);
        const float4 w1 = __ldg(xr4 + (m + 1 > M4LAST ? M4LAST : m + 1));
        const float4 w2 = __ldg(xr4 + (m + 2 > M4LAST ? M4LAST : m + 2));
        const float4 w3 = __ldg(xr4 + (m + 3 > M4LAST ? M4LAST : m + 3));
        octet_row<0>(w0, w1, w2, w3, xq0, xq1, outb, i0, t);
        octet_row<1>(w0, w1, w2, w3, xq0, xq1, outb, i0, t);
        octet_row<2>(w0, w1, w2, w3, xq0, xq1, outb, i0, t);
        octet_row<3>(w0, w1, w2, w3, xq0, xq1, outb, i0, t);
        octet_row<4>(w0, w1, w2, w3, xq0, xq1, outb, i0, t);
        octet_row<5>(w0, w1, w2, w3, xq0, xq1, outb, i0, t);
        octet_row<6>(w0, w1, w2, w3, xq0, xq1, outb, i0, t);
        octet_row<7>(w0, w1, w2, w3, xq0, xq1, outb, i0, t);
    }
}

__global__ __launch_bounds__(THREADS, 12)
void selmul_kernel(const float* __restrict__ x, float* __restrict__ out) {
    const int q   = blockIdx.x;        // 0..63
    const int i0A = 8 * q;             // 0..504
    const int i0B = 1016 - 8 * q;      // 1016..512  (both % 8 == 0)
    const int t   = threadIdx.x;
    const int tr  = THREADS - 1 - t;   // reversed lanes for mirror octet:
                                       // active lanes pack from opposite ends.

    for (int bb = 0; bb < BB; ++bb) {
        const int b = blockIdx.y * BB + bb;
        const float*  xrow = x + b * N;
        const float4* xr4  = reinterpret_cast<const float4*>(xrow);
        float* outb = out + b * TRI;   // max elem offset < 2^27: int-safe

        // Scalar heads + tails for the 16 rows of both octets (<= 6 elems each).
        if (t < 16) {
            const int i0 = (t & 8) ? i0B : i0A;
            const int i  = i0 + (t & 7);
            const int Tn = triang(i + 1);
            const int base = i * N - Tn;
            const int fj = i + ((((Tn & 3) - (i & 3)) + 4) & 3); // first aligned j
            const float xi = __ldg(xrow + i);
            const int he = fj < N ? fj : N;
            for (int j = i; j < he; ++j)
                __stcs(outb + base + j, xi * __ldg(xrow + j));
            const int nv = (N > fj) ? ((N - fj) >> 2) : 0;
            for (int j = fj + 4 * nv; j < N; ++j)
                __stcs(outb + base + j, xi * __ldg(xrow + j));
        }

        octet(xr4, outb, i0A, t);
        octet(xr4, outb, i0B, tr);
    }
}

extern "C" void kernel_launch(void* const* d_in, const int* in_sizes, int n_in,
                              void* d_out, int out_size) {
    (void)in_sizes; (void)n_in; (void)out_size;
    const float* x = (const float*)d_in[0];
    float* out = (float*)d_out;

    dim3 grid(N / 16, B / BB);   // 64 octet-pairs x 64 batch groups = 4096 blocks
    dim3 block(THREADS);
    selmul_kernel<<<grid, block>>>(x, out);
}

// round 11
// speedup vs baseline: 1.3660x; 1.3660x over previous
#include <cuda_runtime.h>

// SelMul: pair (i,j), i<=j, row-major triangular:
//   offset(i,j) = i*N - T(i+1) + j,  T(k) = k(k-1)/2,  value x[b,i]*x[b,j].
// x: (256,1024) fp32 -> out: (256,524800) fp32 (~537 MB). Store-bound.
//
// R10 = R8 geometry (best: 96.4us) with the two mirror octets FUSED so all
// 10 LDG.128 (2x4 window + 2x2 xq) issue before any dependent store ->
// doubles per-thread MLP, covering the L2-hit latency the R8 profile exposed
// (DRAM 65%, issue 28%, nothing saturated). Indexing identical to R8.
//
// Octet rows i0..i0+7, i0%8==0; first aligned j for row r is i0 + D(r),
//   D(r) = r + ((T(r+1)&3 - r) & 3) = {0,1,3,6,6,7,9,8}, max D+3 = 12.
// Window t: w[0..15] = x[i0+4t..i0+4t+15] (4 aligned LDG.128, clamped
// overfetch only feeds predicated-off lanes); row r emits one aligned STG.128
// covering j = i0+D+4t..+3. Heads/tails (<=3+3 elems) scalar, same congruence.

static constexpr int N       = 1024;
static constexpr int B       = 256;
static constexpr int TRI     = N * (N + 1) / 2;   // 524800
static constexpr int BB      = 4;                 // batches per block
static constexpr int THREADS = 256;
static constexpr int M4LAST  = N / 4 - 1;         // 255

__host__ __device__ constexpr int triang(int k) { return k * (k - 1) / 2; }
__host__ __device__ constexpr int Dof(int r) {
    return r + ((((triang(r + 1) & 3) - r) + 8) & 3);
}

template <int K>
__device__ __forceinline__ float pick(const float4& a, const float4& b,
                                      const float4& c, const float4& d) {
    if constexpr (K == 0)  return a.x;
    else if constexpr (K == 1)  return a.y;
    else if constexpr (K == 2)  return a.z;
    else if constexpr (K == 3)  return a.w;
    else if constexpr (K == 4)  return b.x;
    else if constexpr (K == 5)  return b.y;
    else if constexpr (K == 6)  return b.z;
    else if constexpr (K == 7)  return b.w;
    else if constexpr (K == 8)  return c.x;
    else if constexpr (K == 9)  return c.y;
    else if constexpr (K == 10) return c.z;
    else if constexpr (K == 11) return c.w;
    else if constexpr (K == 12) return d.x;
    else if constexpr (K == 13) return d.y;
    else if constexpr (K == 14) return d.z;
    else return d.w;
}

template <int R>
__device__ __forceinline__ void octet_row(bool lane_ok,
                                          const float4& w0, const float4& w1,
                                          const float4& w2, const float4& w3,
                                          const float4& xq0, const float4& xq1,
                                          float* __restrict__ outb,
                                          int i0, int t) {
    constexpr int D = Dof(R);
    const int v = N - i0 - D;            // 4*n_r (may be <= 0 for last octet)
    if (lane_ok && v > 0 && t < (v >> 2)) {
        const int i = i0 + R;
        const float xi = pick<R>(xq0, xq1, xq1, xq1);       // x[i0+R]
        const int base = i * N - triang(i + 1);
        float4 o;
        o.x = pick<D    >(w0, w1, w2, w3) * xi;
        o.y = pick<D + 1>(w0, w1, w2, w3) * xi;
        o.z = pick<D + 2>(w0, w1, w2, w3) * xi;
        o.w = pick<D + 3>(w0, w1, w2, w3) * xi;
        // (base + i0 + D) % 4 == 0 by construction -> aligned STG.128
        __stcs(reinterpret_cast<float4*>(outb + base + i0 + D) + t, o);
    }
}

// Issue the 4 clamped window loads for one octet (no stores).
__device__ __forceinline__ void load_window(const float4* __restrict__ xr4,
                                            int i0, int t,
                                            float4& w0, float4& w1,
                                            float4& w2, float4& w3) {
    // Clamp t too (inactive lanes), then clamp the overfetch words. A clamped
    // slot is only ever consumed by a lane/row whose predicate is false.
    const int tc = t > M4LAST ? M4LAST : t;
    const int m  = (i0 >> 2) + tc;
    const int mc = m > M4LAST ? M4LAST : m;
    w0 = __ldg(xr4 + mc);
    w1 = __ldg(xr4 + (mc + 1 > M4LAST ? M4LAST : mc + 1));
    w2 = __ldg(xr4 + (mc + 2 > M4LAST ? M4LAST : mc + 2));
    w3 = __ldg(xr4 + (mc + 3 > M4LAST ? M4LAST : mc + 3));
}

template <int OC>  // 8 rows of one octet, all predicated (no early return)
__device__ __forceinline__ void store_octet(bool ok,
                                            const float4& w0, const float4& w1,
                                            const float4& w2, const float4& w3,
                                            const float4& xq0, const float4& xq1,
                                            float* __restrict__ outb,
                                            int i0, int t) {
    octet_row<0>(ok, w0, w1, w2, w3, xq0, xq1, outb, i0, t);
    octet_row<1>(ok, w0, w1, w2, w3, xq0, xq1, outb, i0, t);
    octet_row<2>(ok, w0, w1, w2, w3, xq0, xq1, outb, i0, t);
    octet_row<3>(ok, w0, w1, w2, w3, xq0, xq1, outb, i0, t);
    octet_row<4>(ok, w0, w1, w2, w3, xq0, xq1, outb, i0, t);
    octet_row<5>(ok, w0, w1, w2, w3, xq0, xq1, outb, i0, t);
    octet_row<6>(ok, w0, w1, w2, w3, xq0, xq1, outb, i0, t);
    octet_row<7>(ok, w0, w1, w2, w3, xq0, xq1, outb, i0, t);
}

__global__ __launch_bounds__(THREADS)
void selmul_kernel(const float* __restrict__ x, float* __restrict__ out) {
    const int q   = blockIdx.x;        // 0..63
    const int i0A = 8 * q;             // 0..504
    const int i0B = 1016 - 8 * q;      // 1016..512  (both % 8 == 0)
    const int t   = threadIdx.x;
    const int tr  = THREADS - 1 - t;   // reversed lanes for mirror octet

    for (int bb = 0; bb < BB; ++bb) {
        const int b = blockIdx.y * BB + bb;
        const float*  xrow = x + b * N;
        const float4* xr4  = reinterpret_cast<const float4*>(xrow);
        float* outb = out + b * TRI;   // max elem offset < 2^27: int-safe

        // Scalar heads + tails for the 16 rows of both octets (<= 6 elems each).
        if (t < 16) {
            const int i0 = (t & 8) ? i0B : i0A;
            const int i  = i0 + (t & 7);
            const int Tn = triang(i + 1);
            const int base = i * N - Tn;
            const int fj = i + ((((Tn & 3) - (i & 3)) + 4) & 3); // first aligned j
            const float xi = __ldg(xrow + i);
            const int he = fj < N ? fj : N;
            for (int j = i; j < he; ++j)
                __stcs(outb + base + j, xi * __ldg(xrow + j));
            const int nv = (N > fj) ? ((N - fj) >> 2) : 0;
            for (int j = fj + 4 * nv; j < N; ++j)
                __stcs(outb + base + j, xi * __ldg(xrow + j));
        }

        // ---- FUSED: all loads for both octets first (10 independent LDG.128) ----
        const bool okA = t  < ((N - i0A) >> 2);
        const bool okB = tr < ((N - i0B) >> 2);

        float4 a0, a1, a2, a3, b0, b1, b2, b3;
        load_window(xr4, i0A, t,  a0, a1, a2, a3);
        load_window(xr4, i0B, tr, b0, b1, b2, b3);
        const float4 xqA0 = __ldg(xr4 + (i0A >> 2));
        const float4 xqA1 = __ldg(xr4 + (i0A >> 2) + 1);
        const float4 xqB0 = __ldg(xr4 + (i0B >> 2));
        const float4 xqB1 = __ldg(xr4 + (i0B >> 2) + 1);

        // ---- then all stores (predicated, no branches) ----
        store_octet<0>(okA, a0, a1, a2, a3, xqA0, xqA1, outb, i0A, t);
        store_octet<1>(okB, b0, b1, b2, b3, xqB0, xqB1, outb, i0B, tr);
    }
}

extern "C" void kernel_launch(void* const* d_in, const int* in_sizes, int n_in,
                              void* d_out, int out_size) {
    (void)in_sizes; (void)n_in; (void)out_size;
    const float* x = (const float*)d_in[0];
    float* out = (float*)d_out;

    dim3 grid(N / 16, B / BB);   // 64 octet-pairs x 64 batch groups = 4096 blocks
    dim3 block(THREADS);
    selmul_kernel<<<grid, block>>>(x, out);
}